// round 1
// baseline (speedup 1.0000x reference)
#include <cuda_runtime.h>
#include <math.h>

// Problem constants
#define B_   256
#define S_   32
#define D_   64
#define HQ_  128
#define RD_  256
#define AV_  1000

// Tiling
#define TM     64            // rows (pairs) per CTA chunk
#define KB     32            // K chunk for weight staging
#define NCHUNK 16            // (S_*S_)/TM = 1024/64

// Scratch (no cudaMalloc allowed)
__device__ float g_ha[B_ * S_ * RD_];
__device__ float g_hb[B_ * S_ * RD_];
__device__ float g_hqb[B_ * RD_];
__device__ float g_partial[B_ * NCHUNK * RD_];

// ---------------------------------------------------------------------------
// Kernel 1: per-batch precompute of ha = obj@Wa, hb = obj@Wb, hqb = q@Wq + b1
// grid = B_, block = 256 (one thread per RD column)
// ---------------------------------------------------------------------------
__global__ void __launch_bounds__(256) rn_precompute(
    const float* __restrict__ objects,   // (B, S, D)
    const float* __restrict__ q_feat,    // (B, HQ)
    const float* __restrict__ W_r1,      // (2D+HQ, RD) rows: [Wa(64) | Wb(64) | Wq(128)]
    const float* __restrict__ b_r1)      // (RD,)
{
    __shared__ float obj[S_ * D_];   // 32*64 = 2048
    __shared__ float qf[HQ_];

    const int b = blockIdx.x;
    const int t = threadIdx.x;

    for (int idx = t; idx < S_ * D_; idx += 256)
        obj[idx] = objects[b * S_ * D_ + idx];
    for (int idx = t; idx < HQ_; idx += 256)
        qf[idx] = q_feat[b * HQ_ + idx];
    __syncthreads();

    // ha/hb: accumulate over d, 32 s-accumulators each
    float va[S_], vb[S_];
#pragma unroll
    for (int s = 0; s < S_; s++) { va[s] = 0.f; vb[s] = 0.f; }

#pragma unroll 4
    for (int d = 0; d < D_; d++) {
        const float wa = W_r1[d * RD_ + t];
        const float wb = W_r1[(D_ + d) * RD_ + t];
#pragma unroll
        for (int s = 0; s < S_; s++) {
            const float o = obj[s * D_ + d];
            va[s] = fmaf(o, wa, va[s]);
            vb[s] = fmaf(o, wb, vb[s]);
        }
    }
#pragma unroll
    for (int s = 0; s < S_; s++) {
        g_ha[(b * S_ + s) * RD_ + t] = va[s];
        g_hb[(b * S_ + s) * RD_ + t] = vb[s];
    }

    // hqb = q_feat @ Wq + b_r1
    float vq = b_r1[t];
#pragma unroll 4
    for (int k = 0; k < HQ_; k++)
        vq = fmaf(qf[k], W_r1[(2 * D_ + k) * RD_ + t], vq);
    g_hqb[b * RD_ + t] = vq;
}

// ---------------------------------------------------------------------------
// Kernel 2: fused relation MLP (layers r2, r3, r4) + partial row-sum.
// grid = B_*NCHUNK (4096), block = 256.
// SMEM: A0[TM*RD], A1[TM*RD], Ws[KB*RD]  = 160 KB dynamic.
// Each thread computes an 8x8 microtile: rows ty*8+rr, cols tx*8+cc.
// ---------------------------------------------------------------------------
#define SMEM_MAIN_BYTES ((2 * TM * RD_ + KB * RD_) * (int)sizeof(float))

__global__ void __launch_bounds__(256, 1) rn_main(
    const float* __restrict__ W_r2, const float* __restrict__ b_r2,
    const float* __restrict__ W_r3, const float* __restrict__ b_r3,
    const float* __restrict__ W_r4, const float* __restrict__ b_r4)
{
    extern __shared__ float smem[];
    float* A0 = smem;                    // TM*RD
    float* A1 = smem + TM * RD_;         // TM*RD
    float* Ws = smem + 2 * TM * RD_;     // KB*RD

    const int b     = blockIdx.x >> 4;       // / NCHUNK
    const int chunk = blockIdx.x & (NCHUNK - 1);
    const int tid   = threadIdx.x;
    const int ty    = tid >> 5;   // 0..7 (== warp id)
    const int tx    = tid & 31;   // 0..31

    const float* __restrict__ ha  = g_ha  + b * S_ * RD_;
    const float* __restrict__ hb  = g_hb  + b * S_ * RD_;
    const float* __restrict__ hqb = g_hqb + b * RD_;

    // Stage 0: build layer-1 tile  h0[r][t] = relu(ha[i] + hb[j] + hq + b1)
    for (int idx = tid; idx < TM * RD_; idx += 256) {
        const int r = idx >> 8;          // row within chunk
        const int t = idx & (RD_ - 1);
        const int p = chunk * TM + r;    // pair index 0..1023
        const int i = p >> 5;            // p / S_
        const int j = p & (S_ - 1);      // p % S_
        const float v = ha[i * RD_ + t] + hb[j * RD_ + t] + hqb[t];
        A0[idx] = fmaxf(v, 0.f);
    }
    __syncthreads();

    float* Ain  = A0;
    float* Aout = A1;

#pragma unroll 1
    for (int L = 0; L < 3; L++) {
        const float* __restrict__ W  = (L == 0) ? W_r2 : (L == 1) ? W_r3 : W_r4;
        const float* __restrict__ bs = (L == 0) ? b_r2 : (L == 1) ? b_r3 : b_r4;

        float acc[8][8];
#pragma unroll
        for (int rr = 0; rr < 8; rr++)
#pragma unroll
            for (int cc = 0; cc < 8; cc++)
                acc[rr][cc] = 0.f;

#pragma unroll 1
        for (int k0 = 0; k0 < RD_; k0 += KB) {
            // stage weight K-chunk into SMEM (coalesced, L2-resident source)
            for (int idx = tid; idx < KB * RD_; idx += 256)
                Ws[idx] = W[(k0 + (idx >> 8)) * RD_ + (idx & (RD_ - 1))];
            __syncthreads();

#pragma unroll 8
            for (int k = 0; k < KB; k++) {
                const float4 w0 = *(const float4*)&Ws[k * RD_ + tx * 8];
                const float4 w1 = *(const float4*)&Ws[k * RD_ + tx * 8 + 4];
                const float bf[8] = { w0.x, w0.y, w0.z, w0.w,
                                      w1.x, w1.y, w1.z, w1.w };
#pragma unroll
                for (int rr = 0; rr < 8; rr++) {
                    const float a = Ain[(ty * 8 + rr) * RD_ + k0 + k]; // warp-broadcast
#pragma unroll
                    for (int cc = 0; cc < 8; cc++)
                        acc[rr][cc] = fmaf(a, bf[cc], acc[rr][cc]);
                }
            }
            __syncthreads();
        }

        // epilogue: bias + relu, write to Aout
        const float4 bb0 = *(const float4*)&bs[tx * 8];
        const float4 bb1 = *(const float4*)&bs[tx * 8 + 4];
        const float bvec[8] = { bb0.x, bb0.y, bb0.z, bb0.w,
                                bb1.x, bb1.y, bb1.z, bb1.w };
#pragma unroll
        for (int rr = 0; rr < 8; rr++) {
            float4 o0, o1;
            o0.x = fmaxf(acc[rr][0] + bvec[0], 0.f);
            o0.y = fmaxf(acc[rr][1] + bvec[1], 0.f);
            o0.z = fmaxf(acc[rr][2] + bvec[2], 0.f);
            o0.w = fmaxf(acc[rr][3] + bvec[3], 0.f);
            o1.x = fmaxf(acc[rr][4] + bvec[4], 0.f);
            o1.y = fmaxf(acc[rr][5] + bvec[5], 0.f);
            o1.z = fmaxf(acc[rr][6] + bvec[6], 0.f);
            o1.w = fmaxf(acc[rr][7] + bvec[7], 0.f);
            *(float4*)&Aout[(ty * 8 + rr) * RD_ + tx * 8]     = o0;
            *(float4*)&Aout[(ty * 8 + rr) * RD_ + tx * 8 + 4] = o1;
        }
        __syncthreads();

        float* tmp = Ain; Ain = Aout; Aout = tmp;
    }

    // partial column sums of the r4 output tile (deterministic, no atomics)
    const int col = tid;
    float s = 0.f;
#pragma unroll 8
    for (int r = 0; r < TM; r++)
        s += Ain[r * RD_ + col];
    g_partial[blockIdx.x * RD_ + col] = s;
}

// ---------------------------------------------------------------------------
// Kernel 3: reduce partials -> relations, projection MLP, softmax.
// grid = B_, block = 256.
// ---------------------------------------------------------------------------
__global__ void __launch_bounds__(256) rn_tail(
    const float* __restrict__ W_p1, const float* __restrict__ b_p1,
    const float* __restrict__ W_p2, const float* __restrict__ b_p2,
    const float* __restrict__ W_p3, const float* __restrict__ b_p3,
    const float* __restrict__ W_out, const float* __restrict__ b_out,
    float* __restrict__ out)
{
    __shared__ float s0[RD_];
    __shared__ float s1[RD_];
    __shared__ float s29[32];
    __shared__ float red[256];

    const int b = blockIdx.x;
    const int t = threadIdx.x;

    // relations[b][t] = sum over 16 chunks of partial sums
    float rel = 0.f;
#pragma unroll
    for (int c = 0; c < NCHUNK; c++)
        rel += g_partial[(b * NCHUNK + c) * RD_ + t];
    s0[t] = rel;
    __syncthreads();

    // p1
    float v1 = b_p1[t];
#pragma unroll 4
    for (int k = 0; k < RD_; k++)
        v1 = fmaf(s0[k], W_p1[k * 256 + t], v1);
    v1 = fmaxf(v1, 0.f);
    s1[t] = v1;
    __syncthreads();

    // p2
    float v2 = b_p2[t];
#pragma unroll 4
    for (int k = 0; k < 256; k++)
        v2 = fmaf(s1[k], W_p2[k * 256 + t], v2);
    v2 = fmaxf(v2, 0.f);
    __syncthreads();
    s0[t] = v2;
    __syncthreads();

    // p3 (29 outputs)
    if (t < 29) {
        float v3 = b_p3[t];
        for (int k = 0; k < 256; k++)
            v3 = fmaf(s0[k], W_p3[k * 29 + t], v3);
        s29[t] = fmaxf(v3, 0.f);
    }
    __syncthreads();

    // logits over AV_=1000 + softmax
    float lg[4];
    float mx = -1e30f;
#pragma unroll
    for (int u = 0; u < 4; u++) {
        const int v = t + u * 256;
        if (v < AV_) {
            float l = b_out[v];
#pragma unroll
            for (int k = 0; k < 29; k++)
                l = fmaf(s29[k], W_out[k * AV_ + v], l);
            lg[u] = l;
            mx = fmaxf(mx, l);
        } else {
            lg[u] = -1e30f;
        }
    }

    // block max reduce
    red[t] = mx;
    __syncthreads();
    for (int o = 128; o > 0; o >>= 1) {
        if (t < o) red[t] = fmaxf(red[t], red[t + o]);
        __syncthreads();
    }
    mx = red[0];
    __syncthreads();

    // block sum reduce of exp
    float se = 0.f;
#pragma unroll
    for (int u = 0; u < 4; u++) {
        const int v = t + u * 256;
        if (v < AV_) se += expf(lg[u] - mx);
    }
    red[t] = se;
    __syncthreads();
    for (int o = 128; o > 0; o >>= 1) {
        if (t < o) red[t] += red[t + o];
        __syncthreads();
    }
    const float inv = 1.f / red[0];

#pragma unroll
    for (int u = 0; u < 4; u++) {
        const int v = t + u * 256;
        if (v < AV_)
            out[b * AV_ + v] = expf(lg[u] - mx) * inv;
    }
}

// ---------------------------------------------------------------------------
extern "C" void kernel_launch(void* const* d_in, const int* in_sizes, int n_in,
                              void* d_out, int out_size)
{
    const float* objects = (const float*)d_in[0];
    const float* q_feat  = (const float*)d_in[1];
    const float* W_r1    = (const float*)d_in[2];
    const float* b_r1    = (const float*)d_in[3];
    const float* W_r2    = (const float*)d_in[4];
    const float* b_r2    = (const float*)d_in[5];
    const float* W_r3    = (const float*)d_in[6];
    const float* b_r3    = (const float*)d_in[7];
    const float* W_r4    = (const float*)d_in[8];
    const float* b_r4    = (const float*)d_in[9];
    const float* W_p1    = (const float*)d_in[10];
    const float* b_p1    = (const float*)d_in[11];
    const float* W_p2    = (const float*)d_in[12];
    const float* b_p2    = (const float*)d_in[13];
    const float* W_p3    = (const float*)d_in[14];
    const float* b_p3    = (const float*)d_in[15];
    const float* W_out   = (const float*)d_in[16];
    const float* b_out   = (const float*)d_in[17];

    cudaFuncSetAttribute(rn_main, cudaFuncAttributeMaxDynamicSharedMemorySize,
                         SMEM_MAIN_BYTES);

    rn_precompute<<<B_, 256>>>(objects, q_feat, W_r1, b_r1);
    rn_main<<<B_ * NCHUNK, 256, SMEM_MAIN_BYTES>>>(W_r2, b_r2, W_r3, b_r3,
                                                   W_r4, b_r4);
    rn_tail<<<B_, 256>>>(W_p1, b_p1, W_p2, b_p2, W_p3, b_p3,
                         W_out, b_out, (float*)d_out);
}

// round 3
// speedup vs baseline: 1.0002x; 1.0002x over previous
#include <cuda_runtime.h>
#include <math.h>

// Problem constants
#define B_   256
#define S_   32
#define D_   64
#define HQ_  128
#define RD_  256
#define AV_  1000

// Tiling
#define TM     64            // rows (pairs) per CTA chunk
#define KB     32            // K chunk for weight staging
#define NCHUNK 16            // (S_*S_)/TM = 1024/64

// Scratch (no cudaMalloc allowed)
__device__ float g_ha[B_ * S_ * RD_];
__device__ float g_hb[B_ * S_ * RD_];
__device__ float g_hqb[B_ * RD_];
__device__ float g_partial[B_ * NCHUNK * RD_];

// ---------------------------------------------------------------------------
// Kernel 1: per-batch precompute of ha = obj@Wa, hb = obj@Wb, hqb = q@Wq + b1
// grid = B_, block = 256 (one thread per RD column)
// ---------------------------------------------------------------------------
__global__ void __launch_bounds__(256) rn_precompute(
    const float* __restrict__ objects,   // (B, S, D)
    const float* __restrict__ q_feat,    // (B, HQ)
    const float* __restrict__ W_r1,      // (2D+HQ, RD) rows: [Wa(64) | Wb(64) | Wq(128)]
    const float* __restrict__ b_r1)      // (RD,)
{
    __shared__ float obj[S_ * D_];   // 32*64 = 2048
    __shared__ float qf[HQ_];

    const int b = blockIdx.x;
    const int t = threadIdx.x;

    for (int idx = t; idx < S_ * D_; idx += 256)
        obj[idx] = objects[b * S_ * D_ + idx];
    for (int idx = t; idx < HQ_; idx += 256)
        qf[idx] = q_feat[b * HQ_ + idx];
    __syncthreads();

    // ha/hb: accumulate over d, 32 s-accumulators each
    float va[S_], vb[S_];
#pragma unroll
    for (int s = 0; s < S_; s++) { va[s] = 0.f; vb[s] = 0.f; }

#pragma unroll 4
    for (int d = 0; d < D_; d++) {
        const float wa = W_r1[d * RD_ + t];
        const float wb = W_r1[(D_ + d) * RD_ + t];
#pragma unroll
        for (int s = 0; s < S_; s++) {
            const float o = obj[s * D_ + d];
            va[s] = fmaf(o, wa, va[s]);
            vb[s] = fmaf(o, wb, vb[s]);
        }
    }
#pragma unroll
    for (int s = 0; s < S_; s++) {
        g_ha[(b * S_ + s) * RD_ + t] = va[s];
        g_hb[(b * S_ + s) * RD_ + t] = vb[s];
    }

    // hqb = q_feat @ Wq + b_r1
    float vq = b_r1[t];
#pragma unroll 4
    for (int k = 0; k < HQ_; k++)
        vq = fmaf(qf[k], W_r1[(2 * D_ + k) * RD_ + t], vq);
    g_hqb[b * RD_ + t] = vq;
}

// ---------------------------------------------------------------------------
// Kernel 2: fused relation MLP (layers r2, r3, r4) + partial row-sum.
// grid = B_*NCHUNK (4096), block = 256.
// SMEM: A0[TM*RD], A1[TM*RD], Ws[KB*RD]  = 160 KB dynamic.
// Each thread computes an 8x8 microtile: rows ty*8+rr, cols tx*8+cc.
// ---------------------------------------------------------------------------
#define SMEM_MAIN_BYTES ((2 * TM * RD_ + KB * RD_) * (int)sizeof(float))

__global__ void __launch_bounds__(256, 1) rn_main(
    const float* __restrict__ W_r2, const float* __restrict__ b_r2,
    const float* __restrict__ W_r3, const float* __restrict__ b_r3,
    const float* __restrict__ W_r4, const float* __restrict__ b_r4)
{
    extern __shared__ float smem[];
    float* A0 = smem;                    // TM*RD
    float* A1 = smem + TM * RD_;         // TM*RD
    float* Ws = smem + 2 * TM * RD_;     // KB*RD

    const int b     = blockIdx.x >> 4;       // / NCHUNK
    const int chunk = blockIdx.x & (NCHUNK - 1);
    const int tid   = threadIdx.x;
    const int ty    = tid >> 5;   // 0..7 (== warp id)
    const int tx    = tid & 31;   // 0..31

    const float* __restrict__ ha  = g_ha  + b * S_ * RD_;
    const float* __restrict__ hb  = g_hb  + b * S_ * RD_;
    const float* __restrict__ hqb = g_hqb + b * RD_;

    // Stage 0: build layer-1 tile  h0[r][t] = relu(ha[i] + hb[j] + hq + b1)
    for (int idx = tid; idx < TM * RD_; idx += 256) {
        const int r = idx >> 8;          // row within chunk
        const int t = idx & (RD_ - 1);
        const int p = chunk * TM + r;    // pair index 0..1023
        const int i = p >> 5;            // p / S_
        const int j = p & (S_ - 1);      // p % S_
        const float v = ha[i * RD_ + t] + hb[j * RD_ + t] + hqb[t];
        A0[idx] = fmaxf(v, 0.f);
    }
    __syncthreads();

    float* Ain  = A0;
    float* Aout = A1;

#pragma unroll 1
    for (int L = 0; L < 3; L++) {
        const float* __restrict__ W  = (L == 0) ? W_r2 : (L == 1) ? W_r3 : W_r4;
        const float* __restrict__ bs = (L == 0) ? b_r2 : (L == 1) ? b_r3 : b_r4;

        float acc[8][8];
#pragma unroll
        for (int rr = 0; rr < 8; rr++)
#pragma unroll
            for (int cc = 0; cc < 8; cc++)
                acc[rr][cc] = 0.f;

#pragma unroll 1
        for (int k0 = 0; k0 < RD_; k0 += KB) {
            // stage weight K-chunk into SMEM (coalesced, L2-resident source)
            for (int idx = tid; idx < KB * RD_; idx += 256)
                Ws[idx] = W[(k0 + (idx >> 8)) * RD_ + (idx & (RD_ - 1))];
            __syncthreads();

#pragma unroll 8
            for (int k = 0; k < KB; k++) {
                const float4 w0 = *(const float4*)&Ws[k * RD_ + tx * 8];
                const float4 w1 = *(const float4*)&Ws[k * RD_ + tx * 8 + 4];
                const float bf[8] = { w0.x, w0.y, w0.z, w0.w,
                                      w1.x, w1.y, w1.z, w1.w };
#pragma unroll
                for (int rr = 0; rr < 8; rr++) {
                    const float a = Ain[(ty * 8 + rr) * RD_ + k0 + k]; // warp-broadcast
#pragma unroll
                    for (int cc = 0; cc < 8; cc++)
                        acc[rr][cc] = fmaf(a, bf[cc], acc[rr][cc]);
                }
            }
            __syncthreads();
        }

        // epilogue: bias + relu, write to Aout
        const float4 bb0 = *(const float4*)&bs[tx * 8];
        const float4 bb1 = *(const float4*)&bs[tx * 8 + 4];
        const float bvec[8] = { bb0.x, bb0.y, bb0.z, bb0.w,
                                bb1.x, bb1.y, bb1.z, bb1.w };
#pragma unroll
        for (int rr = 0; rr < 8; rr++) {
            float4 o0, o1;
            o0.x = fmaxf(acc[rr][0] + bvec[0], 0.f);
            o0.y = fmaxf(acc[rr][1] + bvec[1], 0.f);
            o0.z = fmaxf(acc[rr][2] + bvec[2], 0.f);
            o0.w = fmaxf(acc[rr][3] + bvec[3], 0.f);
            o1.x = fmaxf(acc[rr][4] + bvec[4], 0.f);
            o1.y = fmaxf(acc[rr][5] + bvec[5], 0.f);
            o1.z = fmaxf(acc[rr][6] + bvec[6], 0.f);
            o1.w = fmaxf(acc[rr][7] + bvec[7], 0.f);
            *(float4*)&Aout[(ty * 8 + rr) * RD_ + tx * 8]     = o0;
            *(float4*)&Aout[(ty * 8 + rr) * RD_ + tx * 8 + 4] = o1;
        }
        __syncthreads();

        float* tmp = Ain; Ain = Aout; Aout = tmp;
    }

    // partial column sums of the r4 output tile (deterministic, no atomics)
    const int col = tid;
    float s = 0.f;
#pragma unroll 8
    for (int r = 0; r < TM; r++)
        s += Ain[r * RD_ + col];
    g_partial[blockIdx.x * RD_ + col] = s;
}

// ---------------------------------------------------------------------------
// Kernel 3: reduce partials -> relations, projection MLP, softmax.
// grid = B_, block = 256.
// ---------------------------------------------------------------------------
__global__ void __launch_bounds__(256) rn_tail(
    const float* __restrict__ W_p1, const float* __restrict__ b_p1,
    const float* __restrict__ W_p2, const float* __restrict__ b_p2,
    const float* __restrict__ W_p3, const float* __restrict__ b_p3,
    const float* __restrict__ W_out, const float* __restrict__ b_out,
    float* __restrict__ out)
{
    __shared__ float s0[RD_];
    __shared__ float s1[RD_];
    __shared__ float s29[32];
    __shared__ float red[256];

    const int b = blockIdx.x;
    const int t = threadIdx.x;

    // relations[b][t] = sum over 16 chunks of partial sums
    float rel = 0.f;
#pragma unroll
    for (int c = 0; c < NCHUNK; c++)
        rel += g_partial[(b * NCHUNK + c) * RD_ + t];
    s0[t] = rel;
    __syncthreads();

    // p1
    float v1 = b_p1[t];
#pragma unroll 4
    for (int k = 0; k < RD_; k++)
        v1 = fmaf(s0[k], W_p1[k * 256 + t], v1);
    v1 = fmaxf(v1, 0.f);
    s1[t] = v1;
    __syncthreads();

    // p2
    float v2 = b_p2[t];
#pragma unroll 4
    for (int k = 0; k < 256; k++)
        v2 = fmaf(s1[k], W_p2[k * 256 + t], v2);
    v2 = fmaxf(v2, 0.f);
    __syncthreads();
    s0[t] = v2;
    __syncthreads();

    // p3 (29 outputs)
    if (t < 29) {
        float v3 = b_p3[t];
        for (int k = 0; k < 256; k++)
            v3 = fmaf(s0[k], W_p3[k * 29 + t], v3);
        s29[t] = fmaxf(v3, 0.f);
    }
    __syncthreads();

    // logits over AV_=1000 + softmax
    float lg[4];
    float mx = -1e30f;
#pragma unroll
    for (int u = 0; u < 4; u++) {
        const int v = t + u * 256;
        if (v < AV_) {
            float l = b_out[v];
#pragma unroll
            for (int k = 0; k < 29; k++)
                l = fmaf(s29[k], W_out[k * AV_ + v], l);
            lg[u] = l;
            mx = fmaxf(mx, l);
        } else {
            lg[u] = -1e30f;
        }
    }

    // block max reduce
    red[t] = mx;
    __syncthreads();
    for (int o = 128; o > 0; o >>= 1) {
        if (t < o) red[t] = fmaxf(red[t], red[t + o]);
        __syncthreads();
    }
    mx = red[0];
    __syncthreads();

    // block sum reduce of exp
    float se = 0.f;
#pragma unroll
    for (int u = 0; u < 4; u++) {
        const int v = t + u * 256;
        if (v < AV_) se += expf(lg[u] - mx);
    }
    red[t] = se;
    __syncthreads();
    for (int o = 128; o > 0; o >>= 1) {
        if (t < o) red[t] += red[t + o];
        __syncthreads();
    }
    const float inv = 1.f / red[0];

#pragma unroll
    for (int u = 0; u < 4; u++) {
        const int v = t + u * 256;
        if (v < AV_)
            out[b * AV_ + v] = expf(lg[u] - mx) * inv;
    }
}

// ---------------------------------------------------------------------------
extern "C" void kernel_launch(void* const* d_in, const int* in_sizes, int n_in,
                              void* d_out, int out_size)
{
    const float* objects = (const float*)d_in[0];
    const float* q_feat  = (const float*)d_in[1];
    const float* W_r1    = (const float*)d_in[2];
    const float* b_r1    = (const float*)d_in[3];
    const float* W_r2    = (const float*)d_in[4];
    const float* b_r2    = (const float*)d_in[5];
    const float* W_r3    = (const float*)d_in[6];
    const float* b_r3    = (const float*)d_in[7];
    const float* W_r4    = (const float*)d_in[8];
    const float* b_r4    = (const float*)d_in[9];
    const float* W_p1    = (const float*)d_in[10];
    const float* b_p1    = (const float*)d_in[11];
    const float* W_p2    = (const float*)d_in[12];
    const float* b_p2    = (const float*)d_in[13];
    const float* W_p3    = (const float*)d_in[14];
    const float* b_p3    = (const float*)d_in[15];
    const float* W_out   = (const float*)d_in[16];
    const float* b_out   = (const float*)d_in[17];

    cudaFuncSetAttribute(rn_main, cudaFuncAttributeMaxDynamicSharedMemorySize,
                         SMEM_MAIN_BYTES);

    rn_precompute<<<B_, 256>>>(objects, q_feat, W_r1, b_r1);
    rn_main<<<B_ * NCHUNK, 256, SMEM_MAIN_BYTES>>>(W_r2, b_r2, W_r3, b_r3,
                                                   W_r4, b_r4);
    rn_tail<<<B_, 256>>>(W_p1, b_p1, W_p2, b_p2, W_p3, b_p3,
                         W_out, b_out, (float*)d_out);
}